// round 1
// baseline (speedup 1.0000x reference)
#include <cuda_runtime.h>

#define LUT5 59049      // 9^5
#define E4   6561       // 9^4
#define HW   (1024*1024)
#define NPIX (4*HW)

// Repacked LUT: entry (e, j), e over dims0..3 (9^4), j = idx4 in [0,8).
// Entry = 16 floats (64B, 2 aligned sectors):
//   [c0@j, c0@j+1, c1@j, c1@j+1, c2@j, c2@j+1, c3@j, c3@j+1, c4@j, c4@j+1, pad x6]
__device__ __align__(64) float g_D[E4 * 8 * 16];   // 3.36 MB

__global__ void pack_kernel(const float* __restrict__ lut) {
    int t = blockIdx.x * blockDim.x + threadIdx.x;
    if (t >= E4 * 8) return;
    int e = t >> 3;       // dims 0..3 combined
    int j = t & 7;        // idx4 base, 0..7
    float* dst = g_D + (size_t)t * 16;
#pragma unroll
    for (int c = 0; c < 5; c++) {
        int src = c * LUT5 + e * 9 + j;
        dst[c * 2 + 0] = lut[src];
        dst[c * 2 + 1] = lut[src + 1];
    }
#pragma unroll
    for (int k = 10; k < 16; k++) dst[k] = 0.0f;
}

__global__ void __launch_bounds__(256)
lut_kernel(const float* __restrict__ x, float* __restrict__ out) {
    int p = blockIdx.x * blockDim.x + threadIdx.x;
    if (p >= NPIX) return;
    int b  = p >> 20;          // p / HW
    int hw = p & (HW - 1);

    const float* xb = x + (size_t)b * 5 * HW + hw;

    int   idx[5];
    float fr[5];
#pragma unroll
    for (int c = 0; c < 5; c++) {
        float xs = xb[(size_t)c * HW] * 8.0f;
        float fi = floorf(xs);
        fi = fminf(fmaxf(fi, 0.0f), 7.0f);
        idx[c] = (int)fi;
        fr[c]  = xs - fi;
    }

    int E = (((idx[0] * 9 + idx[1]) * 9 + idx[2]) * 9 + idx[3]) * 8 + idx[4];

    float g1 = fr[4], g0 = 1.0f - fr[4];
    float w0b = fr[0], w0a = 1.0f - fr[0];
    float w1b = fr[1], w1a = 1.0f - fr[1];
    float w2[2] = {1.0f - fr[2], fr[2]};
    float w3[2] = {1.0f - fr[3], fr[3]};
    float pw[4] = {w0a * w1a, w0a * w1b, w0b * w1a, w0b * w1b};

    float acc0 = 0.f, acc1 = 0.f, acc2 = 0.f, acc3 = 0.f, acc4 = 0.f;
    const float4* Dq = (const float4*)g_D;

#pragma unroll
    for (int c01 = 0; c01 < 4; c01++) {
#pragma unroll
        for (int c2 = 0; c2 < 2; c2++) {
#pragma unroll
            for (int c3 = 0; c3 < 2; c3++) {
                // entry-index offset: (c0*729 + c1*81 + c2*9 + c3) * 8
                int off = (c01 >> 1) * 5832 + (c01 & 1) * 648 + c2 * 72 + c3 * 8;
                int a = (E + off) * 4;            // float4 index
                float4 q0 = Dq[a];                // c0,c1 pairs
                float4 q1 = Dq[a + 1];            // c2,c3 pairs
                float2 q2 = *(const float2*)(Dq + a + 2);  // c4 pair

                float w   = pw[c01] * w2[c2] * w3[c3];
                float wg0 = w * g0;
                float wg1 = w * g1;

                acc0 = fmaf(wg0, q0.x, fmaf(wg1, q0.y, acc0));
                acc1 = fmaf(wg0, q0.z, fmaf(wg1, q0.w, acc1));
                acc2 = fmaf(wg0, q1.x, fmaf(wg1, q1.y, acc2));
                acc3 = fmaf(wg0, q1.z, fmaf(wg1, q1.w, acc3));
                acc4 = fmaf(wg0, q2.x, fmaf(wg1, q2.y, acc4));
            }
        }
    }

    float* ob = out + (size_t)b * 5 * HW + hw;
    ob[0 * HW] = acc0;
    ob[1 * (size_t)HW] = acc1;
    ob[2 * (size_t)HW] = acc2;
    ob[3 * (size_t)HW] = acc3;
    ob[4 * (size_t)HW] = acc4;
}

extern "C" void kernel_launch(void* const* d_in, const int* in_sizes, int n_in,
                              void* d_out, int out_size) {
    // Inputs: x (4*5*1024*1024 floats), LUT (5*59049 = 295245 floats).
    // Identify by size in case ordering differs.
    const float* x   = (const float*)d_in[0];
    const float* lut = (const float*)d_in[1];
    if (n_in >= 2 && in_sizes[0] == 5 * LUT5) {
        lut = (const float*)d_in[0];
        x   = (const float*)d_in[1];
    }
    float* out = (float*)d_out;

    pack_kernel<<<(E4 * 8 + 255) / 256, 256>>>(lut);
    lut_kernel<<<(NPIX + 255) / 256, 256>>>(x, out);
}

// round 2
// speedup vs baseline: 1.1842x; 1.1842x over previous
#include <cuda_runtime.h>
#include <cuda_fp16.h>

#define LUT5 59049      // 9^5
#define HW   (1024*1024)
#define NPIX (4*HW)

#define E2      81          // 9^2 entries over dims 0,1
#define BLK     512         // 8^3 base-index blocks over dims 2,3,4
#define NENT    (E2*BLK)    // 41472 entries
// Entry: 40 fp16 (5 ch x 8 corners of dims 2,3,4), padded to 128B stride.
// Layout within entry: half index c*8 + t, t = c2*4 + c3*2 + c4.
__device__ __align__(128) __half g_D[NENT * 64];   // 5.3 MB

__global__ void pack_kernel(const float* __restrict__ lut) {
    int tid = blockIdx.x * blockDim.x + threadIdx.x;
    if (tid >= NENT * 5) return;
    int e = tid / 5;
    int c = tid - e * 5;
    int i01 = e >> 9;            // 0..80
    int rem = e & 511;
    int b2 = rem >> 6, b3 = (rem >> 3) & 7, b4 = rem & 7;
    int i0 = i01 / 9, i1 = i01 - (i01 / 9) * 9;
    const float* src = lut + c * LUT5 + i0 * 6561 + i1 * 729 + b2 * 81 + b3 * 9 + b4;
    __half* dst = g_D + (size_t)e * 64 + c * 8;
#pragma unroll
    for (int t = 0; t < 8; t++) {
        int t2 = t >> 2, t3 = (t >> 1) & 1, t4 = t & 1;
        dst[t] = __float2half_rn(src[t2 * 81 + t3 * 9 + t4]);
    }
}

__device__ __forceinline__ float dot8(uint4 q, const float* wt) {
    float2 p0 = __half22float2(*(const __half2*)&q.x);
    float2 p1 = __half22float2(*(const __half2*)&q.y);
    float2 p2 = __half22float2(*(const __half2*)&q.z);
    float2 p3 = __half22float2(*(const __half2*)&q.w);
    float s = wt[0] * p0.x;
    s = fmaf(wt[1], p0.y, s);
    s = fmaf(wt[2], p1.x, s);
    s = fmaf(wt[3], p1.y, s);
    s = fmaf(wt[4], p2.x, s);
    s = fmaf(wt[5], p2.y, s);
    s = fmaf(wt[6], p3.x, s);
    s = fmaf(wt[7], p3.y, s);
    return s;
}

__global__ void __launch_bounds__(256)
lut_kernel(const float* __restrict__ x, float* __restrict__ out) {
    int p = blockIdx.x * blockDim.x + threadIdx.x;
    if (p >= NPIX) return;
    int b  = p >> 20;
    int hw = p & (HW - 1);

    const float* xb = x + (size_t)b * 5 * HW + hw;

    int   idx[5];
    float fr[5];
#pragma unroll
    for (int c = 0; c < 5; c++) {
        float xs = xb[(size_t)c * HW] * 8.0f;
        float fi = floorf(xs);
        fi = fminf(fmaxf(fi, 0.0f), 7.0f);
        idx[c] = (int)fi;
        fr[c]  = xs - fi;
    }

    // entry index for base corner (dims 0,1 gridded 9x9; dims 2,3,4 blocked 8^3)
    int ent = (idx[0] * 9 + idx[1]) * BLK + idx[2] * 64 + idx[3] * 8 + idx[4];
    int base4 = ent * 8;   // uint4 units (128B / 16B)

    float w0a = 1.0f - fr[0], w0b = fr[0];
    float w1a = 1.0f - fr[1], w1b = fr[1];
    float w2a = 1.0f - fr[2], w2b = fr[2];
    float w3a = 1.0f - fr[3], w3b = fr[3];
    float w4a = 1.0f - fr[4], w4b = fr[4];

    float pw[4] = {w0a * w1a, w0a * w1b, w0b * w1a, w0b * w1b};
    float wt[8];
    wt[0] = w2a * w3a * w4a;  wt[1] = w2a * w3a * w4b;
    wt[2] = w2a * w3b * w4a;  wt[3] = w2a * w3b * w4b;
    wt[4] = w2b * w3a * w4a;  wt[5] = w2b * w3a * w4b;
    wt[6] = w2b * w3b * w4a;  wt[7] = w2b * w3b * w4b;

    const uint4* Dq = (const uint4*)g_D;
    float acc0 = 0.f, acc1 = 0.f, acc2 = 0.f, acc3 = 0.f, acc4 = 0.f;

#pragma unroll
    for (int c01 = 0; c01 < 4; c01++) {
        int a = base4 + (c01 >> 1) * (9 * BLK * 8) + (c01 & 1) * (BLK * 8);
        uint4 q0 = Dq[a + 0];
        uint4 q1 = Dq[a + 1];
        uint4 q2 = Dq[a + 2];
        uint4 q3 = Dq[a + 3];
        uint4 q4 = Dq[a + 4];
        float w = pw[c01];
        acc0 = fmaf(w, dot8(q0, wt), acc0);
        acc1 = fmaf(w, dot8(q1, wt), acc1);
        acc2 = fmaf(w, dot8(q2, wt), acc2);
        acc3 = fmaf(w, dot8(q3, wt), acc3);
        acc4 = fmaf(w, dot8(q4, wt), acc4);
    }

    float* ob = out + (size_t)b * 5 * HW + hw;
    ob[0 * (size_t)HW] = acc0;
    ob[1 * (size_t)HW] = acc1;
    ob[2 * (size_t)HW] = acc2;
    ob[3 * (size_t)HW] = acc3;
    ob[4 * (size_t)HW] = acc4;
}

extern "C" void kernel_launch(void* const* d_in, const int* in_sizes, int n_in,
                              void* d_out, int out_size) {
    const float* x   = (const float*)d_in[0];
    const float* lut = (const float*)d_in[1];
    if (n_in >= 2 && in_sizes[0] == 5 * LUT5) {
        lut = (const float*)d_in[0];
        x   = (const float*)d_in[1];
    }
    float* out = (float*)d_out;

    pack_kernel<<<(NENT * 5 + 255) / 256, 256>>>(lut);
    lut_kernel<<<(NPIX + 255) / 256, 256>>>(x, out);
}

// round 3
// speedup vs baseline: 2.4593x; 2.0767x over previous
#include <cuda_runtime.h>
#include <cuda_fp16.h>

#define LUT5 59049      // 9^5
#define HW   (1024*1024)
#define NPIX (4*HW)

#define E2      81          // 9^2 entries over dims 0,1
#define BLK     512         // 8^3 base-index blocks over dims 2,3,4
#define NENT    (E2*BLK)    // 41472 entries
// Entry: 40 fp16 (5 ch x 8 corners of dims 2,3,4), padded to 128B stride (one L2 line).
// Half index within entry: c*8 + t, t = c2*4 + c3*2 + c4.
__device__ __align__(128) __half g_D[NENT * 64];   // 5.3 MB

__global__ void pack_kernel(const float* __restrict__ lut) {
    int tid = blockIdx.x * blockDim.x + threadIdx.x;
    if (tid >= NENT * 5) return;
    int e = tid / 5;
    int c = tid - e * 5;
    int i01 = e >> 9;            // 0..80
    int rem = e & 511;
    int b2 = rem >> 6, b3 = (rem >> 3) & 7, b4 = rem & 7;
    int i0 = i01 / 9, i1 = i01 - (i01 / 9) * 9;
    const float* src = lut + c * LUT5 + i0 * 6561 + i1 * 729 + b2 * 81 + b3 * 9 + b4;
    __half* dst = g_D + (size_t)e * 64 + c * 8;
#pragma unroll
    for (int t = 0; t < 8; t++) {
        int t2 = t >> 2, t3 = (t >> 1) & 1, t4 = t & 1;
        dst[t] = __float2half_rn(src[t2 * 81 + t3 * 9 + t4]);
    }
}

__device__ __forceinline__ float dot8(uint4 q, const float* wt) {
    float2 p0 = __half22float2(*(const __half2*)&q.x);
    float2 p1 = __half22float2(*(const __half2*)&q.y);
    float2 p2 = __half22float2(*(const __half2*)&q.z);
    float2 p3 = __half22float2(*(const __half2*)&q.w);
    float s = wt[0] * p0.x;
    s = fmaf(wt[1], p0.y, s);
    s = fmaf(wt[2], p1.x, s);
    s = fmaf(wt[3], p1.y, s);
    s = fmaf(wt[4], p2.x, s);
    s = fmaf(wt[5], p2.y, s);
    s = fmaf(wt[6], p3.x, s);
    s = fmaf(wt[7], p3.y, s);
    return s;
}

// 8 lanes per pixel: sub-lane l handles channel chunk l of each 128B corner entry.
// 4 pixels per warp, 32 pixels per 256-thread block.
__global__ void __launch_bounds__(256)
lut_kernel(const float* __restrict__ x, float* __restrict__ out) {
    int lane = threadIdx.x & 31;
    int l    = lane & 7;                      // sub-lane within 8-lane group
    int gw   = (blockIdx.x * blockDim.x + threadIdx.x) >> 5;   // global warp
    int p    = gw * 4 + (lane >> 3);          // pixel id
    int b    = p >> 20;
    int hw   = p & (HW - 1);

    // Each of lanes 0..4 loads its channel's x value (lanes 5..7 duplicate ch4, in-bounds).
    int ce = l < 5 ? l : 4;
    float xv = x[(size_t)(b * 5 + ce) * HW + hw];
    float xs = xv * 8.0f;
    float xsc = fminf(fmaxf(xs, 0.0f), 7.9999995f);   // idx+frac packed; clamp

    // Broadcast all 5 dims within the 8-lane group.
    float v0 = __shfl_sync(0xffffffffu, xsc, 0, 8);
    float v1 = __shfl_sync(0xffffffffu, xsc, 1, 8);
    float v2 = __shfl_sync(0xffffffffu, xsc, 2, 8);
    float v3 = __shfl_sync(0xffffffffu, xsc, 3, 8);
    float v4 = __shfl_sync(0xffffffffu, xsc, 4, 8);

    float f0 = floorf(v0), f1 = floorf(v1), f2 = floorf(v2), f3 = floorf(v3), f4 = floorf(v4);
    int i0 = (int)f0, i1 = (int)f1, i2 = (int)f2, i3 = (int)f3, i4 = (int)f4;
    float fr0 = v0 - f0, fr1 = v1 - f1, fr2 = v2 - f2, fr3 = v3 - f3, fr4 = v4 - f4;

    int ent = ((i0 * 9 + i1) << 9) + (i2 << 6) + (i3 << 3) + i4;

    float w0a = 1.0f - fr0, w0b = fr0;
    float w1a = 1.0f - fr1, w1b = fr1;
    float w2a = 1.0f - fr2, w2b = fr2;
    float w3a = 1.0f - fr3, w3b = fr3;
    float w4a = 1.0f - fr4, w4b = fr4;

    float pw0 = w0a * w1a, pw1 = w0a * w1b, pw2 = w0b * w1a, pw3 = w0b * w1b;
    float t0 = w2a * w3a, t1 = w2a * w3b, t2 = w2b * w3a, t3 = w2b * w3b;
    float wt[8];
    wt[0] = t0 * w4a;  wt[1] = t0 * w4b;
    wt[2] = t1 * w4a;  wt[3] = t1 * w4b;
    wt[4] = t2 * w4a;  wt[5] = t2 * w4b;
    wt[6] = t3 * w4a;  wt[7] = t3 * w4b;

    const uint4* Dq = (const uint4*)g_D;
    // 4 corners over dims 0,1. All 8 lanes of a group read the SAME 128B line.
    int e0 = (ent) * 8 + l;
    int e1 = (ent + BLK) * 8 + l;
    int e2_ = (ent + 9 * BLK) * 8 + l;
    int e3 = (ent + 10 * BLK) * 8 + l;
    uint4 q0 = Dq[e0];
    uint4 q1 = Dq[e1];
    uint4 q2 = Dq[e2_];
    uint4 q3 = Dq[e3];

    float acc;
    acc = pw0 * dot8(q0, wt);
    acc = fmaf(pw1, dot8(q1, wt), acc);
    acc = fmaf(pw2, dot8(q2, wt), acc);
    acc = fmaf(pw3, dot8(q3, wt), acc);

    if (l < 5)
        out[(size_t)(b * 5 + l) * HW + hw] = acc;
}

extern "C" void kernel_launch(void* const* d_in, const int* in_sizes, int n_in,
                              void* d_out, int out_size) {
    const float* x   = (const float*)d_in[0];
    const float* lut = (const float*)d_in[1];
    if (n_in >= 2 && in_sizes[0] == 5 * LUT5) {
        lut = (const float*)d_in[0];
        x   = (const float*)d_in[1];
    }
    float* out = (float*)d_out;

    pack_kernel<<<(NENT * 5 + 255) / 256, 256>>>(lut);
    // 4 pixels per warp, 32 per block
    lut_kernel<<<NPIX / 32, 256>>>(x, out);
}

// round 4
// speedup vs baseline: 3.3015x; 1.3425x over previous
#include <cuda_runtime.h>
#include <cuda_fp16.h>

#define LUT5 59049      // 9^5
#define HW   (1024*1024)
#define NPIX (4*HW)

#define E2      81          // 9^2 entries over dims 0,1
#define BLK     512         // 8^3 base-index blocks over dims 2,3,4
#define NENT    (E2*BLK)    // 41472 entries
// Entry: 40 fp16 (5 ch x 8 corners of dims 2,3,4), padded to 128B stride (one L2 line).
// Half index within entry: c*8 + t, t = c2*4 + c3*2 + c4.
__device__ __align__(128) __half g_D[NENT * 64];   // 5.3 MB

__global__ void pack_kernel(const float* __restrict__ lut) {
    int tid = blockIdx.x * blockDim.x + threadIdx.x;
    if (tid >= NENT * 5) return;
    int e = tid / 5;
    int c = tid - e * 5;
    int i01 = e >> 9;            // 0..80
    int rem = e & 511;
    int b2 = rem >> 6, b3 = (rem >> 3) & 7, b4 = rem & 7;
    int i0 = i01 / 9, i1 = i01 - (i01 / 9) * 9;
    const float* src = lut + c * LUT5 + i0 * 6561 + i1 * 729 + b2 * 81 + b3 * 9 + b4;
    __half* dst = g_D + (size_t)e * 64 + c * 8;
#pragma unroll
    for (int t = 0; t < 8; t++) {
        int t2 = t >> 2, t3 = (t >> 1) & 1, t4 = t & 1;
        dst[t] = __float2half_rn(src[t2 * 81 + t3 * 9 + t4]);
    }
}

__device__ __forceinline__ float dot8(uint4 q, const float* wt) {
    float2 p0 = __half22float2(*(const __half2*)&q.x);
    float2 p1 = __half22float2(*(const __half2*)&q.y);
    float2 p2 = __half22float2(*(const __half2*)&q.z);
    float2 p3 = __half22float2(*(const __half2*)&q.w);
    float s = wt[0] * p0.x;
    s = fmaf(wt[1], p0.y, s);
    s = fmaf(wt[2], p1.x, s);
    s = fmaf(wt[3], p1.y, s);
    s = fmaf(wt[4], p2.x, s);
    s = fmaf(wt[5], p2.y, s);
    s = fmaf(wt[6], p3.x, s);
    s = fmaf(wt[7], p3.y, s);
    return s;
}

// 5 lanes per pixel (one per channel), 6 pixels per warp, lanes 30/31 idle-duplicate.
__global__ void __launch_bounds__(256)
lut_kernel(const float* __restrict__ x, float* __restrict__ out) {
    int lane = threadIdx.x & 31;
    int g  = lane / 5;  if (g > 5) g = 5;      // pixel group 0..5
    int ch = lane - g * 5;                     // channel 0..4 (5,6 for lanes 30/31)
    int che = ch > 4 ? 4 : ch;
    int gw = (blockIdx.x * blockDim.x + threadIdx.x) >> 5;   // global warp
    int p  = gw * 6 + g;                       // pixel id
    int pc = p < NPIX ? p : NPIX - 1;          // clamped for addressing
    int b  = pc >> 20;
    int hw = pc & (HW - 1);

    float xv = x[(size_t)(b * 5 + che) * HW + hw];
    float xs = xv * 8.0f;
    float xsc = fminf(fmaxf(xs, 0.0f), 7.9999995f);

    // Broadcast the 5 channel values within the 5-lane group (absolute src lanes).
    int base = g * 5;
    float v0 = __shfl_sync(0xffffffffu, xsc, base + 0);
    float v1 = __shfl_sync(0xffffffffu, xsc, base + 1);
    float v2 = __shfl_sync(0xffffffffu, xsc, base + 2);
    float v3 = __shfl_sync(0xffffffffu, xsc, base + 3);
    float v4 = __shfl_sync(0xffffffffu, xsc, base + 4);

    float f0 = floorf(v0), f1 = floorf(v1), f2 = floorf(v2), f3 = floorf(v3), f4 = floorf(v4);
    int i0 = (int)f0, i1 = (int)f1, i2 = (int)f2, i3 = (int)f3, i4 = (int)f4;
    float fr0 = v0 - f0, fr1 = v1 - f1, fr2 = v2 - f2, fr3 = v3 - f3, fr4 = v4 - f4;

    int ent = ((i0 * 9 + i1) << 9) + (i2 << 6) + (i3 << 3) + i4;

    float w0a = 1.0f - fr0, w0b = fr0;
    float w1a = 1.0f - fr1, w1b = fr1;
    float w2a = 1.0f - fr2, w2b = fr2;
    float w3a = 1.0f - fr3, w3b = fr3;
    float w4a = 1.0f - fr4, w4b = fr4;

    float pw0 = w0a * w1a, pw1 = w0a * w1b, pw2 = w0b * w1a, pw3 = w0b * w1b;
    float t0 = w2a * w3a, t1 = w2a * w3b, t2 = w2b * w3a, t3 = w2b * w3b;
    float wt[8];
    wt[0] = t0 * w4a;  wt[1] = t0 * w4b;
    wt[2] = t1 * w4a;  wt[3] = t1 * w4b;
    wt[4] = t2 * w4a;  wt[5] = t2 * w4b;
    wt[6] = t3 * w4a;  wt[7] = t3 * w4b;

    const uint4* Dq = (const uint4*)g_D;
    // 4 corners over dims 0,1. All 5 lanes of a group read the SAME 128B line.
    uint4 q0 = Dq[(ent)            * 8 + che];
    uint4 q1 = Dq[(ent + BLK)      * 8 + che];
    uint4 q2 = Dq[(ent + 9 * BLK)  * 8 + che];
    uint4 q3 = Dq[(ent + 10 * BLK) * 8 + che];

    float acc;
    acc = pw0 * dot8(q0, wt);
    acc = fmaf(pw1, dot8(q1, wt), acc);
    acc = fmaf(pw2, dot8(q2, wt), acc);
    acc = fmaf(pw3, dot8(q3, wt), acc);

    if (ch < 5 && p < NPIX)
        out[(size_t)(b * 5 + ch) * HW + hw] = acc;
}

extern "C" void kernel_launch(void* const* d_in, const int* in_sizes, int n_in,
                              void* d_out, int out_size) {
    const float* x   = (const float*)d_in[0];
    const float* lut = (const float*)d_in[1];
    if (n_in >= 2 && in_sizes[0] == 5 * LUT5) {
        lut = (const float*)d_in[0];
        x   = (const float*)d_in[1];
    }
    float* out = (float*)d_out;

    pack_kernel<<<(NENT * 5 + 255) / 256, 256>>>(lut);

    int warps  = (NPIX + 5) / 6;              // 6 pixels per warp
    int blocks = (warps * 32 + 255) / 256;
    lut_kernel<<<blocks, 256>>>(x, out);
}

// round 6
// speedup vs baseline: 3.3217x; 1.0061x over previous
#include <cuda_runtime.h>
#include <cuda_fp16.h>

#define LUT5 59049      // 9^5
#define HW   (1024*1024)
#define NPIX (4*HW)

#define E2      81          // 9^2 entries over dims 0,1
#define BLK     512         // 8^3 base-index blocks over dims 2,3,4
#define NENT    (E2*BLK)    // 41472 entries
// Entry: 40 fp16 (5 ch x 8 corners of dims 2,3,4), padded to 128B stride (one line).
// Half index within entry: c*8 + t, t = c2*4 + c3*2 + c4. Halves 40..63 unused (zero).
__device__ __align__(128) __half g_D[NENT * 64];   // 5.3 MB

// One thread per (c, e), e fast. Scalar loads: lut + c*59049 is only 4B-aligned
// (59049 odd), so float2 loads would fault for odd c.
__global__ void pack_kernel(const float* __restrict__ lut) {
    int tid = blockIdx.x * blockDim.x + threadIdx.x;
    if (tid >= NENT * 5) return;
    int c = tid / NENT;
    int e = tid - c * NENT;
    int i01 = e >> 9;            // 0..80
    int rem = e & 511;
    int b2 = rem >> 6, b3 = (rem >> 3) & 7, b4 = rem & 7;
    int i0 = i01 / 9, i1 = i01 - (i01 / 9) * 9;
    const float* src = lut + c * LUT5 + i0 * 6561 + i1 * 729 + b2 * 81 + b3 * 9 + b4;

    __half2 h0 = __floats2half2_rn(src[0],  src[1]);    // c2=0 c3=0
    __half2 h1 = __floats2half2_rn(src[9],  src[10]);   // c2=0 c3=1
    __half2 h2 = __floats2half2_rn(src[81], src[82]);   // c2=1 c3=0
    __half2 h3 = __floats2half2_rn(src[90], src[91]);   // c2=1 c3=1

    uint4 v;
    v.x = *(unsigned*)&h0;  v.y = *(unsigned*)&h1;
    v.z = *(unsigned*)&h2;  v.w = *(unsigned*)&h3;
    *(uint4*)(g_D + (size_t)e * 64 + c * 8) = v;   // 16B-aligned dst
}

__device__ __forceinline__ float dot8h(uint4 q, __half2 w0, __half2 w1,
                                       __half2 w2, __half2 w3) {
    __half2 s = __hmul2(*(const __half2*)&q.x, w0);
    s = __hfma2(*(const __half2*)&q.y, w1, s);
    s = __hfma2(*(const __half2*)&q.z, w2, s);
    s = __hfma2(*(const __half2*)&q.w, w3, s);
    float2 f = __half22float2(s);
    return f.x + f.y;
}

// 5 lanes per pixel (one per channel), 6 pixels per warp, lanes 30/31 idle-duplicate.
__global__ void __launch_bounds__(256)
lut_kernel(const float* __restrict__ x, float* __restrict__ out) {
    int lane = threadIdx.x & 31;
    int g  = lane / 5;  if (g > 5) g = 5;      // pixel group 0..5
    int ch = lane - g * 5;                     // channel 0..4 (5,6 for lanes 30/31)
    int che = ch > 4 ? 4 : ch;
    int gw = (blockIdx.x * blockDim.x + threadIdx.x) >> 5;   // global warp
    int p  = gw * 6 + g;                       // pixel id
    int pc = p < NPIX ? p : NPIX - 1;          // clamped for addressing
    int b  = pc >> 20;
    int hw = pc & (HW - 1);

    float xv = x[(size_t)(b * 5 + che) * HW + hw];
    float xs = xv * 8.0f;
    float xsc = fminf(fmaxf(xs, 0.0f), 7.9999995f);

    // Broadcast the 5 channel values within the 5-lane group (absolute src lanes).
    int base = g * 5;
    float v0 = __shfl_sync(0xffffffffu, xsc, base + 0);
    float v1 = __shfl_sync(0xffffffffu, xsc, base + 1);
    float v2 = __shfl_sync(0xffffffffu, xsc, base + 2);
    float v3 = __shfl_sync(0xffffffffu, xsc, base + 3);
    float v4 = __shfl_sync(0xffffffffu, xsc, base + 4);

    float f0 = floorf(v0), f1 = floorf(v1), f2 = floorf(v2), f3 = floorf(v3), f4 = floorf(v4);
    int i0 = (int)f0, i1 = (int)f1, i2 = (int)f2, i3 = (int)f3, i4 = (int)f4;
    float fr0 = v0 - f0, fr1 = v1 - f1, fr2 = v2 - f2, fr3 = v3 - f3, fr4 = v4 - f4;

    int ent = ((i0 * 9 + i1) << 9) + (i2 << 6) + (i3 << 3) + i4;

    float w0a = 1.0f - fr0, w0b = fr0;
    float w1a = 1.0f - fr1, w1b = fr1;
    float w2a = 1.0f - fr2, w2b = fr2;
    float w3a = 1.0f - fr3, w3b = fr3;
    float w4a = 1.0f - fr4, w4b = fr4;

    float pw0 = w0a * w1a, pw1 = w0a * w1b, pw2 = w0b * w1a, pw3 = w0b * w1b;
    float t0 = w2a * w3a, t1 = w2a * w3b, t2 = w2b * w3a, t3 = w2b * w3b;

    // Corner weights over dims 2,3,4 as 4 half2 (pairs along c4).
    __half2 cw0 = __floats2half2_rn(t0 * w4a, t0 * w4b);
    __half2 cw1 = __floats2half2_rn(t1 * w4a, t1 * w4b);
    __half2 cw2 = __floats2half2_rn(t2 * w4a, t2 * w4b);
    __half2 cw3 = __floats2half2_rn(t3 * w4a, t3 * w4b);

    const uint4* Dq = (const uint4*)g_D;
    // 4 corners over dims 0,1. All 5 lanes of a group read the SAME 128B line.
    uint4 q0 = Dq[(ent)            * 8 + che];
    uint4 q1 = Dq[(ent + BLK)      * 8 + che];
    uint4 q2 = Dq[(ent + 9 * BLK)  * 8 + che];
    uint4 q3 = Dq[(ent + 10 * BLK) * 8 + che];

    float acc;
    acc = pw0 * dot8h(q0, cw0, cw1, cw2, cw3);
    acc = fmaf(pw1, dot8h(q1, cw0, cw1, cw2, cw3), acc);
    acc = fmaf(pw2, dot8h(q2, cw0, cw1, cw2, cw3), acc);
    acc = fmaf(pw3, dot8h(q3, cw0, cw1, cw2, cw3), acc);

    if (ch < 5 && p < NPIX)
        out[(size_t)(b * 5 + ch) * HW + hw] = acc;
}

extern "C" void kernel_launch(void* const* d_in, const int* in_sizes, int n_in,
                              void* d_out, int out_size) {
    const float* x   = (const float*)d_in[0];
    const float* lut = (const float*)d_in[1];
    if (n_in >= 2 && in_sizes[0] == 5 * LUT5) {
        lut = (const float*)d_in[0];
        x   = (const float*)d_in[1];
    }
    float* out = (float*)d_out;

    pack_kernel<<<(NENT * 5 + 255) / 256, 256>>>(lut);

    int warps  = (NPIX + 5) / 6;              // 6 pixels per warp
    int blocks = (warps * 32 + 255) / 256;
    lut_kernel<<<blocks, 256>>>(x, out);
}

// round 7
// speedup vs baseline: 3.5526x; 1.0695x over previous
#include <cuda_runtime.h>
#include <cuda_fp16.h>

#define LUT5 59049      // 9^5
#define HW   (1024*1024)
#define NPIX (4*HW)

#define BLK     512         // 8^3 base-index blocks over dims 2,3,4
#define NENT    (81*BLK)    // 41472 entries
// Entry: 40 fp16 (5 ch x 8 corners of dims 2,3,4), padded to 128B stride (one line).
// Half index within entry: c*8 + t, t = c2*4 + c3*2 + c4. Halves 40..63 unused (zero).
__device__ __align__(128) __half g_D[NENT * 64];   // 5.3 MB

// One thread per (c, e), e fast. Scalar loads: lut + c*59049 is only 4B-aligned
// (59049 odd), so float2 loads would fault for odd c.
__global__ void pack_kernel(const float* __restrict__ lut) {
    int tid = blockIdx.x * blockDim.x + threadIdx.x;
    if (tid >= NENT * 5) return;
    int c = tid / NENT;
    int e = tid - c * NENT;
    int i01 = e >> 9;            // 0..80
    int rem = e & 511;
    int b2 = rem >> 6, b3 = (rem >> 3) & 7, b4 = rem & 7;
    int i0 = i01 / 9, i1 = i01 - (i01 / 9) * 9;
    const float* src = lut + c * LUT5 + i0 * 6561 + i1 * 729 + b2 * 81 + b3 * 9 + b4;

    __half2 h0 = __floats2half2_rn(src[0],  src[1]);    // c2=0 c3=0
    __half2 h1 = __floats2half2_rn(src[9],  src[10]);   // c2=0 c3=1
    __half2 h2 = __floats2half2_rn(src[81], src[82]);   // c2=1 c3=0
    __half2 h3 = __floats2half2_rn(src[90], src[91]);   // c2=1 c3=1

    uint4 v;
    v.x = *(unsigned*)&h0;  v.y = *(unsigned*)&h1;
    v.z = *(unsigned*)&h2;  v.w = *(unsigned*)&h3;
    *(uint4*)(g_D + (size_t)e * 64 + c * 8) = v;   // 16B-aligned dst
}

__device__ __forceinline__ float dot8h(uint4 q, __half2 w0, __half2 w1,
                                       __half2 w2, __half2 w3) {
    __half2 s = __hmul2(*(const __half2*)&q.x, w0);
    s = __hfma2(*(const __half2*)&q.y, w1, s);
    s = __hfma2(*(const __half2*)&q.z, w2, s);
    s = __hfma2(*(const __half2*)&q.w, w3, s);
    float2 f = __half22float2(s);
    return f.x + f.y;
}

// Warp owns 32 consecutive pixels. Coalesced load of 5 channel planes (1 line each),
// 6 compute batches of 5-lane groups, shfl in/out redistribution, coalesced stores.
__global__ void __launch_bounds__(256)
lut_kernel(const float* __restrict__ x, float* __restrict__ out) {
    const unsigned FULL = 0xffffffffu;
    int lane = threadIdx.x & 31;
    int gw   = (blockIdx.x * blockDim.x + threadIdx.x) >> 5;
    int p    = gw * 32 + lane;              // this lane's owned pixel
    int b    = p >> 20;
    int hw   = p & (HW - 1);
    size_t iobase = (size_t)b * 5 * HW + hw;   // warp-aligned: hw ≡ lane (mod 32)

    // Coalesced: lane holds all 5 channels of its pixel, pre-scaled+clamped.
    float xs0 = fminf(fmaxf(x[iobase + 0 * (size_t)HW] * 8.0f, 0.0f), 7.9999995f);
    float xs1 = fminf(fmaxf(x[iobase + 1 * (size_t)HW] * 8.0f, 0.0f), 7.9999995f);
    float xs2 = fminf(fmaxf(x[iobase + 2 * (size_t)HW] * 8.0f, 0.0f), 7.9999995f);
    float xs3 = fminf(fmaxf(x[iobase + 3 * (size_t)HW] * 8.0f, 0.0f), 7.9999995f);
    float xs4 = fminf(fmaxf(x[iobase + 4 * (size_t)HW] * 8.0f, 0.0f), 7.9999995f);

    int g  = lane / 5; if (g > 5) g = 5;    // compute group 0..5
    int ch = lane - g * 5;
    int che = ch > 4 ? 4 : ch;
    int myk = lane / 6;                      // batch in which this lane's pixel is computed
    int gs  = lane - myk * 6;                // its group index in that batch

    const uint4* Dq = (const uint4*)g_D;
    float ores[5];

#pragma unroll
    for (int k = 0; k < 6; k++) {
        int q = 6 * k + g;                   // pixel-in-warp this group handles
        bool active = q < 32;                // batch 5: only groups 0,1 real
        int qs = active ? q : 31;

        float v0 = __shfl_sync(FULL, xs0, qs);
        float v1 = __shfl_sync(FULL, xs1, qs);
        float v2 = __shfl_sync(FULL, xs2, qs);
        float v3 = __shfl_sync(FULL, xs3, qs);
        float v4 = __shfl_sync(FULL, xs4, qs);

        float f0 = floorf(v0), f1 = floorf(v1), f2 = floorf(v2),
              f3 = floorf(v3), f4 = floorf(v4);
        int i0 = (int)f0, i1 = (int)f1, i2 = (int)f2, i3 = (int)f3, i4 = (int)f4;
        float fr0 = v0 - f0, fr1 = v1 - f1, fr2 = v2 - f2,
              fr3 = v3 - f3, fr4 = v4 - f4;

        int ent = ((i0 * 9 + i1) << 9) + (i2 << 6) + (i3 << 3) + i4;

        float w0a = 1.0f - fr0, w0b = fr0;
        float w1a = 1.0f - fr1, w1b = fr1;
        float w2a = 1.0f - fr2, w2b = fr2;
        float w3a = 1.0f - fr3, w3b = fr3;
        float w4a = 1.0f - fr4, w4b = fr4;

        float pw0 = w0a * w1a, pw1 = w0a * w1b, pw2 = w0b * w1a, pw3 = w0b * w1b;
        float t0 = w2a * w3a, t1 = w2a * w3b, t2 = w2b * w3a, t3 = w2b * w3b;

        __half2 cw0 = __floats2half2_rn(t0 * w4a, t0 * w4b);
        __half2 cw1 = __floats2half2_rn(t1 * w4a, t1 * w4b);
        __half2 cw2 = __floats2half2_rn(t2 * w4a, t2 * w4b);
        __half2 cw3 = __floats2half2_rn(t3 * w4a, t3 * w4b);

        float acc = 0.0f;
        if (active) {
            uint4 q0 = Dq[(ent)            * 8 + che];
            uint4 q1 = Dq[(ent + BLK)      * 8 + che];
            uint4 q2 = Dq[(ent + 9 * BLK)  * 8 + che];
            uint4 q3 = Dq[(ent + 10 * BLK) * 8 + che];
            acc = pw0 * dot8h(q0, cw0, cw1, cw2, cw3);
            acc = fmaf(pw1, dot8h(q1, cw0, cw1, cw2, cw3), acc);
            acc = fmaf(pw2, dot8h(q2, cw0, cw1, cw2, cw3), acc);
            acc = fmaf(pw3, dot8h(q3, cw0, cw1, cw2, cw3), acc);
        }

        // Scatter this batch's 6 pixels x 5 channels back to owner lanes.
        bool mine = (k == myk);
#pragma unroll
        for (int c = 0; c < 5; c++) {
            float s = __shfl_sync(FULL, acc, (gs * 5 + c) & 31);
            if (mine) ores[c] = s;
        }
    }

    // Coalesced stores: one aligned 128B line per channel plane.
    out[iobase + 0 * (size_t)HW] = ores[0];
    out[iobase + 1 * (size_t)HW] = ores[1];
    out[iobase + 2 * (size_t)HW] = ores[2];
    out[iobase + 3 * (size_t)HW] = ores[3];
    out[iobase + 4 * (size_t)HW] = ores[4];
}

extern "C" void kernel_launch(void* const* d_in, const int* in_sizes, int n_in,
                              void* d_out, int out_size) {
    const float* x   = (const float*)d_in[0];
    const float* lut = (const float*)d_in[1];
    if (n_in >= 2 && in_sizes[0] == 5 * LUT5) {
        lut = (const float*)d_in[0];
        x   = (const float*)d_in[1];
    }
    float* out = (float*)d_out;

    pack_kernel<<<(NENT * 5 + 255) / 256, 256>>>(lut);

    // 32 pixels per warp, 8 warps per block; NPIX divisible by 256*... exactly.
    int blocks = NPIX / (32 * 8);
    lut_kernel<<<blocks, 256>>>(x, out);
}